// round 17
// baseline (speedup 1.0000x reference)
#include <cuda_runtime.h>
#include <cstdint>

// Problem constants
#define N_   5000
#define D_   128
#define T_   100
#define K_   20
#define KQ   5             // quarter-K pipeline granularity
#define EPSV 1e-8f
#define KT_  (K_ * T_)

// GEMM tiling: block step = 32n x 16d x 32t
#define NT 32
#define DT 16
#define TC 32
#define NTB 256
#define NTILES 157         // ceil(5000/32)
#define ZSPLIT 9           // 8 x 4 x 9 = 288 blocks = one wave @ 2/SM
#define STEPS  18

// smem: th[3][KQ][NT][TC] f32 (3x20KB) + ph [K][DT/2][TC] f2 (40KB) + ev[2]
#define TH_Q_F   (KQ * NT * TC)          // 5120 floats per buffer
#define TH_Q_B   (TH_Q_F * 4)            // 20480 bytes
#define PH_F2    (K_ * (DT / 2) * TC)    // 5120 float2
#define EV_INTS  (NT * DT)               // 512 ints per buffer
#define SMEM_BYTES (3 * TH_Q_B + PH_F2 * 8 + 2 * EV_INTS * 4)   // ~104.4KB

__device__ float g_phip_scratch[K_ * D_ * T_];
__device__ float g_theta_scratch[N_ * K_ * T_];

// ---- cp.async helpers ----
__device__ __forceinline__ void cpa16(uint32_t d, const float* s, bool p) {
    asm volatile("cp.async.cg.shared.global [%0], [%1], 16, %2;"
                 :: "r"(d), "l"(s), "r"(p ? 16 : 0));
}
__device__ __forceinline__ void cpa8(uint32_t d, const int* s, bool p) {
    asm volatile("cp.async.ca.shared.global [%0], [%1], 8, %2;"
                 :: "r"(d), "l"(s), "r"(p ? 8 : 0));
}
#define CPCOMMIT() asm volatile("cp.async.commit_group;")
#define CPWAIT0()  asm volatile("cp.async.wait_group 0;")
#define CPWAIT1()  asm volatile("cp.async.wait_group 1;")

// ---------------------------------------------------------------------------
// Kernel 1: phi_prob = sigmoid(phi)
// ---------------------------------------------------------------------------
__global__ void sigmoid_kernel(const float4* __restrict__ phi,
                               float4* __restrict__ out) {
    int i = blockIdx.x * blockDim.x + threadIdx.x;
    if (i < (K_ * D_ * T_) / 4) {
        float4 v = phi[i];
        v.x = __fdividef(1.0f, 1.0f + __expf(-v.x));
        v.y = __fdividef(1.0f, 1.0f + __expf(-v.y));
        v.z = __fdividef(1.0f, 1.0f + __expf(-v.z));
        v.w = __fdividef(1.0f, 1.0f + __expf(-v.w));
        out[i] = v;
    }
}

// ---------------------------------------------------------------------------
// Kernel 2: theta = softmax_K(lambda)
// ---------------------------------------------------------------------------
__global__ __launch_bounds__(256)
void softmax_kernel(const float* __restrict__ lam,
                    float* __restrict__ theta) {
    int idx = blockIdx.x * 256 + threadIdx.x;
    if (idx >= N_ * T_) return;
    int n = idx / T_;
    int t = idx - n * T_;
    const float* src = lam + n * KT_ + t;
    float v[K_];
    #pragma unroll
    for (int k = 0; k < K_; ++k) v[k] = src[k * T_];
    float m = v[0];
    #pragma unroll
    for (int k = 1; k < K_; ++k) m = fmaxf(m, v[k]);
    float s = 0.0f;
    #pragma unroll
    for (int k = 0; k < K_; ++k) { v[k] = __expf(v[k] - m); s += v[k]; }
    float inv = __fdividef(1.0f, s);
    float* dst = theta + n * KT_ + t;
    #pragma unroll
    for (int k = 0; k < K_; ++k) dst[k * T_] = v[k] * inv;
}

// ---------------------------------------------------------------------------
// Kernel 3: pi = clip(mask * (theta @ phi_prob))
//   Crossbar-balanced 8n x 4 d-pair thread tile (R15) + DEPTH-2 pipeline:
//   3 rotating theta quarter-buffers, cp.async wait_group 1 -> each fetch
//   has ~2 quarter-GEMMs of latency cover. evt double-buffered by step parity.
// ---------------------------------------------------------------------------
__global__ __launch_bounds__(NTB, 2)
void gemm_kernel(const float* __restrict__ theta_g,
                 const float* __restrict__ phip,
                 const int*   __restrict__ evt,
                 float*       __restrict__ pi) {
    extern __shared__ float smem[];
    float*  s_th = smem;                                    // [3][KQ][NT][TC]
    float2* s_ph = (float2*)(smem + 3 * TH_Q_F);            // [K][DT/2][TC]
    int*    s_ev = (int*)(smem + 3 * TH_Q_F + PH_F2 * 2);   // [2][NT][DT]

    const uint32_t u_th = (uint32_t)__cvta_generic_to_shared(s_th);
    const uint32_t u_ev = (uint32_t)__cvta_generic_to_shared(s_ev);

    const int tid = threadIdx.x;
    const int d0 = blockIdx.x * DT;
    const int t0 = blockIdx.y * TC;

    // ---- theta chunk descriptors: thread owns (ni, t-quad jj), kk = r ----
    const int  ni  = tid >> 3;                   // 0..31
    const int  jj  = tid & 7;                    // t-quad
    const bool tvj = (t0 + 4 * jj < T_);
    const float*   pth = theta_g + ni * KT_ + t0 + 4 * jj;
    const uint32_t dth = (uint32_t)(ni * (TC * 4) + 16 * jj);
    const uint32_t dev = (uint32_t)(ni * (DT * 4) + 8 * jj);

    // issue one theta quarter (q) of tile starting at n0 into buffer addr tgt
    auto issueQ = [&](uint32_t tgt, int n0, int q) {
        const float* s = pth + n0 * KT_ + q * (KQ * T_);
        bool pv = tvj && (n0 + ni < N_);
        #pragma unroll
        for (int r = 0; r < 5; ++r)
            cpa16(tgt + dth + r * (NT * TC * 4), s + r * T_, pv);
    };

    // ---- prologue: issue Q0 (+evt0) and Q1 BEFORE the phi load ----
    const int n0_first = blockIdx.z * NT;
    issueQ(u_th, n0_first, 0);
    cpa8(u_ev + dev, evt + (size_t)(n0_first + ni) * D_ + d0 + 2 * jj,
         n0_first + ni < N_);
    CPCOMMIT();
    issueQ(u_th + TH_Q_B, n0_first, 1);
    CPCOMMIT();

    // ---- phi tile: load once (d-pairs interleaved as float2) ----
    #pragma unroll
    for (int r = 0; r < 5; ++r) {
        int f  = tid + r * NTB;          // 0..1279
        int j  = f & 7;
        int dp = (f >> 3) & 7;
        int k  = f >> 6;                 // 0..19
        int t  = t0 + 4 * j;
        float4 a = make_float4(0.f, 0.f, 0.f, 0.f);
        float4 b = a;
        if (t < T_) {
            const float* base = phip + k * (D_ * T_) + (d0 + 2 * dp) * T_ + t;
            a = *reinterpret_cast<const float4*>(base);
            b = *reinterpret_cast<const float4*>(base + T_);
        }
        float2* dst = &s_ph[(k * (DT / 2) + dp) * TC + 4 * j];
        dst[0] = make_float2(a.x, b.x);
        dst[1] = make_float2(a.y, b.y);
        dst[2] = make_float2(a.z, b.z);
        dst[3] = make_float2(a.w, b.w);
    }

    const int w    = tid >> 5;
    const int lane = tid & 31;       // lane == t
    const int nb   = (w >> 1) * 8;   // 0,8,16,24
    const int pb   = (w & 1) * 4;    // 0 or 4
    const int t    = t0 + lane;
    const bool tvl = (t < T_);

    int cur = 0;   // rotating buffer index of the quarter being consumed

    for (int st = 0; st < STEPS; ++st) {
        int n0  = (blockIdx.z + st * ZSPLIT) * NT;
        int n0n = n0 + ZSPLIT * NT;

        unsigned long long acc[8][4];
        #pragma unroll
        for (int i = 0; i < 8; ++i)
            #pragma unroll
            for (int p = 0; p < 4; ++p) acc[i][p] = 0ULL;

        #pragma unroll
        for (int q = 0; q < 4; ++q) {
            CPWAIT1();           // quarter q landed (q+1 may be in flight)
            __syncthreads();     // publish; buffer (cur+2)%3 free to overwrite

            // issue quarter q+2 (into buffer cur+2 mod 3)
            int b2 = cur + 2; if (b2 >= 3) b2 -= 3;
            uint32_t tgt = u_th + (uint32_t)b2 * TH_Q_B;
            if (q == 0)      issueQ(tgt, n0, 2);
            else if (q == 1) issueQ(tgt, n0, 3);
            else if (q == 2) {
                issueQ(tgt, n0n, 0);
                cpa8(u_ev + (uint32_t)((st + 1) & 1) * (EV_INTS * 4) + dev,
                     evt + (size_t)(n0n + ni) * D_ + d0 + 2 * jj,
                     n0n + ni < N_);
            } else           issueQ(tgt, n0n, 1);
            CPCOMMIT();

            // ---- GEMM quarter q from buffer cur ----
            const float* thq = smem + cur * TH_Q_F;
            #pragma unroll
            for (int kh = 0; kh < KQ; ++kh) {
                unsigned long long b2v[4];
                const float2* ph = &s_ph[((q * KQ + kh) * (DT / 2) + pb) * TC + lane];
                #pragma unroll
                for (int p = 0; p < 4; ++p)
                    b2v[p] = *reinterpret_cast<const unsigned long long*>(&ph[p * TC]);
                const float* th = &thq[(kh * NT + nb) * TC + lane];
                #pragma unroll
                for (int i = 0; i < 8; ++i) {
                    float a = th[i * TC];
                    unsigned long long a2;
                    asm("mov.b64 %0, {%1, %1};" : "=l"(a2) : "f"(a));
                    #pragma unroll
                    for (int p = 0; p < 4; ++p)
                        asm("fma.rn.f32x2 %0, %1, %2, %0;"
                            : "+l"(acc[i][p]) : "l"(a2), "l"(b2v[p]));
                }
            }
            cur = (cur == 2) ? 0 : cur + 1;
        }

        // ---- epilogue: mask, clip, streaming stores ----
        const int* evb = s_ev + (st & 1) * EV_INTS;
        #pragma unroll
        for (int i = 0; i < 8; ++i) {
            int n = n0 + nb + i;
            if (n >= N_) continue;
            float* prow = pi + (size_t)n * (D_ * T_);
            #pragma unroll
            for (int p = 0; p < 4; ++p) {
                float v0, v1;
                asm("mov.b64 {%0, %1}, %2;" : "=f"(v0), "=f"(v1)
                    : "l"(acc[i][p]));
                int c  = (pb + p) * 2;
                int e0 = evb[(nb + i) * DT + c];
                int e1 = evb[(nb + i) * DT + c + 1];
                v0 = (t <= e0) ? v0 : 0.0f;
                v1 = (t <= e1) ? v1 : 0.0f;
                v0 = fminf(fmaxf(v0, EPSV), 1.0f - EPSV);
                v1 = fminf(fmaxf(v1, EPSV), 1.0f - EPSV);
                if (tvl) {
                    __stcs(&prow[(d0 + c) * T_ + t], v0);
                    __stcs(&prow[(d0 + c + 1) * T_ + t], v1);
                }
            }
        }
    }
    CPWAIT0();   // drain in-flight prefetches before CTA exit
}

// ---------------------------------------------------------------------------
// Launch
// ---------------------------------------------------------------------------
extern "C" void kernel_launch(void* const* d_in, const int* in_sizes, int n_in,
                              void* d_out, int out_size) {
    const float* lam = (const float*)d_in[0];  // [N,K,T] f32
    const float* phi = (const float*)d_in[1];  // [K,D,T] f32
    const int*   evt = (const int*)d_in[2];    // [N,D]   i32

    const long long PI_SZ  = (long long)N_ * D_ * T_;
    const long long TH_SZ  = (long long)N_ * K_ * T_;
    const long long PHP_SZ = (long long)K_ * D_ * T_;

    float* out   = (float*)d_out;
    float* pi    = out;
    float* theta = out + PI_SZ;
    float* phip  = out + PI_SZ + TH_SZ;

    const long long osz = (long long)out_size;
    if (osz < PI_SZ + TH_SZ)
        cudaGetSymbolAddress((void**)&theta, g_theta_scratch);
    if (osz < PI_SZ + TH_SZ + PHP_SZ)
        cudaGetSymbolAddress((void**)&phip, g_phip_scratch);

    // 1) phi_prob = sigmoid(phi)
    int nvec = (K_ * D_ * T_) / 4;
    sigmoid_kernel<<<(nvec + 255) / 256, 256>>>((const float4*)phi,
                                                (float4*)phip);

    // 2) theta = softmax(lambda)
    int npts = N_ * T_;
    softmax_kernel<<<(npts + 255) / 256, 256>>>(lam, theta);

    // 3) pi = mask*clip(theta @ phi_prob)
    cudaFuncSetAttribute(gemm_kernel,
                         cudaFuncAttributeMaxDynamicSharedMemorySize,
                         SMEM_BYTES);
    dim3 grid(D_ / DT, (T_ + TC - 1) / TC, ZSPLIT);  // 8 x 4 x 9 = 288
    gemm_kernel<<<grid, NTB, SMEM_BYTES>>>(theta, phip, evt, pi);
}